// round 15
// baseline (speedup 1.0000x reference)
#include <cuda_runtime.h>
#include <cuda_fp16.h>
#include <stdint.h>

// ---------------------------------------------------------------------------
// SeqFCEncoder via warp-level mma.sync (compute_103 base ISA).
// R15: E-split — each CTA computes 64 rows x 128 of the 256 out-cols
//      (GEMM1/h duplicated across the pair, +20% MMA total), acc2 halves to
//      32 regs -> 3 CTAs/SM (24 warps) for latency hiding. Weights via
//      fragment-order LDG.128 (R11). 1-pass fp16; rel_err must stay
//      0.0004093658 (identical per-element accumulation order).
// ---------------------------------------------------------------------------

typedef unsigned int u32;
typedef unsigned long long u64;

#define B_TOTAL   262144
#define LSEQ      50
#define HDIM      1024
#define EDIM      256
#define MTILE     64
#define NTHREADS  256
#define KC        64
#define NCHUNK    (HDIM / KC)     // 16

// ---- smem layout (bytes, dynamic) ----
#define SM_X     0               // 8KB  X fp16 [64 m][64 k] SW128
#define SM_H0    8192            // 8KB  h buffer 0
#define SM_H1    16384           // 8KB  h buffer 1
#define SM_STAGE 24576           // 13.3KB fp32 staging (pre-loop only)
#define SMEM_TOTAL 38912         // 3 x 38K = 114K < 228K -> 3 CTAs/SM

// ---- fragment-order weight images (same as R11) ----
__device__ __align__(16) u32 g_w1frag[NCHUNK][4][4][32][4];   // 128KB
__device__ __align__(16) u32 g_w2frag[NCHUNK][4][16][32][4];  // 512KB

// ============================ low-level helpers =============================
__device__ __forceinline__ u32 smem_u32_of(const void* p) {
  u32 a;
  asm("{ .reg .u64 t; cvta.to.shared.u64 t, %1; cvt.u32.u64 %0, t; }" : "=r"(a) : "l"(p));
  return a;
}
__device__ __forceinline__ u32 swz(int r, int k) {
  u32 off = ((u32)(r >> 3) << 10) | ((u32)(r & 7) << 7) | ((u32)k << 1);
  return off ^ ((off >> 3) & 0x70u);
}
__device__ __forceinline__ void ldsm4(u32 addr, u32 f[4]) {
  asm volatile("ldmatrix.sync.aligned.m8n8.x4.shared.b16 {%0,%1,%2,%3}, [%4];"
               : "=r"(f[0]), "=r"(f[1]), "=r"(f[2]), "=r"(f[3]) : "r"(addr));
}
__device__ __forceinline__ u32 a_addr(u32 img, int m0, int k0, int lr, int lg) {
  return img + swz(m0 + lr + ((lg & 1) << 3), k0 + ((lg >> 1) << 3));
}
__device__ __forceinline__ void mma16816(float c[4], const u32 a[4], u32 b0, u32 b1) {
  asm volatile(
    "mma.sync.aligned.m16n8k16.row.col.f32.f16.f16.f32 "
    "{%0,%1,%2,%3}, {%4,%5,%6,%7}, {%8,%9}, {%0,%1,%2,%3};"
    : "+f"(c[0]), "+f"(c[1]), "+f"(c[2]), "+f"(c[3])
    : "r"(a[0]), "r"(a[1]), "r"(a[2]), "r"(a[3]), "r"(b0), "r"(b1));
}

// ============================ threefry dropout ==============================
__device__ __forceinline__ u32 rotl32(u32 x, u32 r) { return __funnelshift_l(x, x, r); }
__device__ __forceinline__ void tf2x32(u32 x0, u32 x1, u32 &o0, u32 &o1) {
  const u32 ks0 = 0u, ks1 = 42u, ks2 = 0u ^ 42u ^ 0x1BD11BDAu;
  x0 += ks0; x1 += ks1;
#define TFR(r) { x0 += x1; x1 = rotl32(x1, r); x1 ^= x0; }
  TFR(13) TFR(15) TFR(26) TFR(6)
  x0 += ks1; x1 += ks2 + 1u;
  TFR(17) TFR(29) TFR(16) TFR(24)
  x0 += ks2; x1 += ks0 + 2u;
  TFR(13) TFR(15) TFR(26) TFR(6)
  x0 += ks0; x1 += ks1 + 3u;
  TFR(17) TFR(29) TFR(16) TFR(24)
  x0 += ks1; x1 += ks2 + 4u;
  TFR(13) TFR(15) TFR(26) TFR(6)
  x0 += ks2; x1 += ks0 + 5u;
#undef TFR
  o0 = x0; o1 = x1;
}
__device__ __forceinline__ bool drop_elem(u32 i) {   // validated rel_err 0.0 (R1)
  u32 o0, o1;
  tf2x32(0u, i, o0, o1);
  u32 bits = o0 ^ o1;
  float u = __uint_as_float((bits >> 9) | 0x3f800000u) - 1.0f;
  return u < 0.2f;
}

__device__ __forceinline__ u32 pack_h2(float a, float b) {
  return (u32)__half_as_ushort(__float2half_rn(a))
       | ((u32)__half_as_ushort(__float2half_rn(b)) << 16);
}

// ============================ prep kernel ===================================
// Pack W1/W2 (fp16-rounded) into per-lane MMA B-fragment order.
__global__ void prep_kernel(const float* __restrict__ W1,
                            const float* __restrict__ W2) {
  int idx = blockIdx.x * blockDim.x + threadIdx.x;
  const int NW1 = NCHUNK * 4 * 4 * 32 * 4;    // 32768 u32
  const int NW2 = NCHUNK * 4 * 16 * 32 * 4;   // 131072 u32
  if (idx < NW1) {
    int r = idx & 3, lane = (idx >> 2) & 31;
    int nt = (idx >> 7) & 3, kt = (idx >> 9) & 3, kc = idx >> 11;
    int gid = lane >> 2, tig = lane & 3;
    int n = nt * 16 + gid + ((r & 2) ? 8 : 0);
    int k = kt * 16 + 2 * tig + ((r & 1) ? 8 : 0);
    float w0 = (k     < LSEQ) ? W1[(size_t)k       * HDIM + kc * KC + n] : 0.0f;
    float w1 = (k + 1 < LSEQ) ? W1[(size_t)(k + 1) * HDIM + kc * KC + n] : 0.0f;
    g_w1frag[kc][kt][nt][lane][r] = pack_h2(w0, w1);
  } else if (idx < NW1 + NW2) {
    int j = idx - NW1;
    int r = j & 3, lane = (j >> 2) & 31;
    int nt = (j >> 7) & 15, kt = (j >> 11) & 3, kc = j >> 13;
    int gid = lane >> 2, tig = lane & 3;
    int n = nt * 16 + gid + ((r & 2) ? 8 : 0);
    int k = kc * KC + kt * 16 + 2 * tig + ((r & 1) ? 8 : 0);
    g_w2frag[kc][kt][nt][lane][r] =
        pack_h2(W2[(size_t)k * EDIM + n], W2[(size_t)(k + 1) * EDIM + n]);
  }
}

// ============================ main kernel ===================================
extern __shared__ __align__(1024) unsigned char smem_raw[];

__global__ void __launch_bounds__(NTHREADS, 3)
seqfc_main(const float* __restrict__ seq,
           const float* __restrict__ b1,
           const float* __restrict__ b2,
           float* __restrict__ out)
{
  const int tid  = threadIdx.x;
  const int wid  = tid >> 5;
  const int lane = tid & 31;
  const int lr   = lane & 7;
  const int lg   = lane >> 3;
  const int gid  = lane >> 2;
  const int tig  = lane & 3;
  const int wr   = wid >> 2;          // 2 row groups of 32
  const int wc   = wid & 3;           // 4 col groups
  const int row0 = (blockIdx.x >> 1) * MTILE;
  const int eh   = blockIdx.x & 1;    // E-half: cols [eh*128, eh*128+128)

  const u32 sm = smem_u32_of(smem_raw);

  // ---- X stage: fp32 staging -> mask+dropout -> fp16 SW128 image ----
  {
    float* xs = (float*)(smem_raw + SM_STAGE);     // stride 52
    const float* sp = seq + (size_t)row0 * LSEQ;
    for (int idx = tid; idx < MTILE * LSEQ; idx += NTHREADS) {
      int r = idx / LSEQ, k = idx - r * LSEQ;
      xs[r * 52 + k] = sp[idx];
    }
    __syncthreads();

    const int xrow = tid >> 2;          // 4 threads per row
    const int q    = tid & 3;
    float xv[16];
#pragma unroll
    for (int i = 0; i < 16; ++i) {
      int k = q * 16 + i;
      xv[i] = (k < LSEQ) ? xs[xrow * 52 + k] : 0.0f;
    }
    int f = LSEQ;
#pragma unroll
    for (int i = 15; i >= 0; --i) {
      int k = q * 16 + i;
      if (k < LSEQ && xv[i] == -1.0f) f = k;
    }
    f = min(f, __shfl_xor_sync(0xffffffffu, f, 1));
    f = min(f, __shfl_xor_sync(0xffffffffu, f, 2));
    const u32 gb = (u32)(row0 + xrow) * (u32)LSEQ;
#pragma unroll
    for (int i = 0; i < 16; ++i) {
      int k = q * 16 + i;
      if (k < f && drop_elem(gb + (u32)k)) xv[i] = 0.0f;
    }
#pragma unroll
    for (int c = 0; c < 8; ++c) {
      u32 o = swz(xrow, q * 16 + 2 * c);
      *(u32*)(smem_raw + SM_X + o) = pack_h2(xv[2 * c], xv[2 * c + 1]);
    }
  }
  __syncthreads();            // X image ready

  // ---- GEMM2 accumulators: warp tile = 32 rows x 32 cols (32 regs) ----
  float acc2[2][4][4];
#pragma unroll
  for (int mt = 0; mt < 2; ++mt)
#pragma unroll
    for (int j = 0; j < 4; ++j)
#pragma unroll
      for (int q = 0; q < 4; ++q) acc2[mt][j][q] = 0.0f;

  // ---- chunk loop: ONE __syncthreads per chunk (h double-buffered) ----
  for (int kc = 0; kc < NCHUNK; ++kc) {
    // bias for this chunk's convert
    float bv[4];
    {
      const int bb = kc * KC;
#pragma unroll
      for (int j = 0; j < 2; ++j) {
        int cc = bb + wc * 16 + j * 8 + 2 * tig;
        bv[j * 2]     = __ldg(b1 + cc);
        bv[j * 2 + 1] = __ldg(b1 + cc + 1);
      }
    }

    // ---- GEMM1(kc): warp tile 32 x 16 (identical in both E-half CTAs) ----
    float acc1[2][2][4];
#pragma unroll
    for (int mt = 0; mt < 2; ++mt)
#pragma unroll
      for (int j = 0; j < 2; ++j)
#pragma unroll
        for (int q = 0; q < 4; ++q) acc1[mt][j][q] = 0.0f;

#pragma unroll
    for (int kt = 0; kt < 4; ++kt) {
      const int k0 = kt * 16;
      u32 ax0[4], ax1[4];
      ldsm4(a_addr(sm + SM_X, wr * 32,      k0, lr, lg), ax0);
      ldsm4(a_addr(sm + SM_X, wr * 32 + 16, k0, lr, lg), ax1);
      const uint4 bw = __ldg((const uint4*)g_w1frag[kc][kt][wc][lane]);
      mma16816(acc1[0][0], ax0, bw.x, bw.y);
      mma16816(acc1[0][1], ax0, bw.z, bw.w);
      mma16816(acc1[1][0], ax1, bw.x, bw.y);
      mma16816(acc1[1][1], ax1, bw.z, bw.w);
    }

    // ---- convert: bias + relu -> h fp16 image (buffer kc&1) ----
    const u32 hoff = (u32)(SM_H0 + ((kc & 1) << 13));
#pragma unroll
    for (int mt = 0; mt < 2; ++mt) {
      const int r0 = wr * 32 + mt * 16 + gid;
#pragma unroll
      for (int j = 0; j < 2; ++j) {
        const int cc = wc * 16 + j * 8 + 2 * tig;
        float v0 = fmaxf(acc1[mt][j][0] + bv[j * 2],     0.0f);
        float v1 = fmaxf(acc1[mt][j][1] + bv[j * 2 + 1], 0.0f);
        float v2 = fmaxf(acc1[mt][j][2] + bv[j * 2],     0.0f);
        float v3 = fmaxf(acc1[mt][j][3] + bv[j * 2 + 1], 0.0f);
        *(u32*)(smem_raw + hoff + swz(r0, cc))     = pack_h2(v0, v1);
        *(u32*)(smem_raw + hoff + swz(r0 + 8, cc)) = pack_h2(v2, v3);
      }
    }
    __syncthreads();          // h[kc] visible (also fences prior-buf reuse)

    // ---- GEMM2(kc): warp tile 32 x 32 over this CTA's E-half ----
#pragma unroll
    for (int kt = 0; kt < 4; ++kt) {
      const int k0 = kt * 16;
      u32 ah0[4], ah1[4];
      ldsm4(a_addr(sm + hoff, wr * 32,      k0, lr, lg), ah0);
      ldsm4(a_addr(sm + hoff, wr * 32 + 16, k0, lr, lg), ah1);
#pragma unroll
      for (int t = 0; t < 2; ++t) {
        const int nt = eh * 8 + wc * 2 + t;
        const uint4 bw = __ldg((const uint4*)g_w2frag[kc][kt][nt][lane]);
        mma16816(acc2[0][2*t],     ah0, bw.x, bw.y);
        mma16816(acc2[0][2*t + 1], ah0, bw.z, bw.w);
        mma16816(acc2[1][2*t],     ah1, bw.x, bw.y);
        mma16816(acc2[1][2*t + 1], ah1, bw.z, bw.w);
      }
    }
    // no trailing bar: next chunk writes the other h buffer.
  }

  // ---- epilogue: + b2 (__ldg), store this CTA's 128 columns ----
#pragma unroll
  for (int mt = 0; mt < 2; ++mt) {
    const int r0 = row0 + wr * 32 + mt * 16 + gid;
#pragma unroll
    for (int j = 0; j < 4; ++j) {
      const int c = eh * 128 + wc * 32 + j * 8 + 2 * tig;
      const float bb0 = __ldg(b2 + c), bb1 = __ldg(b2 + c + 1);
      float2 va = make_float2(acc2[mt][j][0] + bb0, acc2[mt][j][1] + bb1);
      float2 vb = make_float2(acc2[mt][j][2] + bb0, acc2[mt][j][3] + bb1);
      *(float2*)(out + (size_t)r0 * EDIM + c)       = va;
      *(float2*)(out + (size_t)(r0 + 8) * EDIM + c) = vb;
    }
  }
}

// ============================ launch ========================================
extern "C" void kernel_launch(void* const* d_in, const int* in_sizes, int n_in,
                              void* d_out, int out_size) {
  (void)in_sizes; (void)n_in; (void)out_size;
  const float* seq = (const float*)d_in[0];
  const float* W1  = (const float*)d_in[1];
  const float* b1  = (const float*)d_in[2];
  const float* W2  = (const float*)d_in[3];
  const float* b2  = (const float*)d_in[4];

  cudaFuncSetAttribute(seqfc_main, cudaFuncAttributeMaxDynamicSharedMemorySize,
                       SMEM_TOTAL);

  const int prep_total = NCHUNK * 4 * 4 * 32 * 4 + NCHUNK * 4 * 16 * 32 * 4;
  prep_kernel<<<(prep_total + 255) / 256, 256>>>(W1, W2);
  seqfc_main<<<(B_TOTAL / MTILE) * 2, NTHREADS, SMEM_TOTAL>>>(seq, b1, b2,
                                                             (float*)d_out);
}

// round 16
// speedup vs baseline: 1.3013x; 1.3013x over previous
#include <cuda_runtime.h>
#include <cuda_fp16.h>
#include <stdint.h>

// ---------------------------------------------------------------------------
// SeqFCEncoder via warp-level mma.sync (compute_103 base ISA).
// R16: R11 (best, 519us) with KC=128 twin-sub-block GEMM1: two sequential
//      32x16 GEMM1 blocks (acc1 stays 16 regs — the shape that never spilled)
//      feed a 16KB h buffer; ONE bar per 128 k-units (8 bars total vs 16).
//      All per-k traffic rates identical to R11. Weights via fragment-order
//      LDG.128. 1-pass fp16; rel_err must stay 0.0004093658.
// ---------------------------------------------------------------------------

typedef unsigned int u32;
typedef unsigned long long u64;

#define B_TOTAL   262144
#define LSEQ      50
#define HDIM      1024
#define EDIM      256
#define MTILE     64
#define NTHREADS  256
#define KC        128
#define NCHUNK    (HDIM / KC)     // 8

// ---- smem layout (bytes, dynamic) ----
#define SM_X     0               // 8KB   X fp16 [64 m][64 k] SW128
#define SM_H0    8192            // 16KB  h buffer 0 (two 8KB 64-k sub-images)
#define SM_H1    24576           // 16KB  h buffer 1
#define SM_STAGE 40960           // 13.3KB fp32 staging (pre-loop only)
#define SMEM_TOTAL 55296         // -> 2 CTAs/SM

// ---- fragment-order weight images ----
__device__ __align__(16) u32 g_w1frag[NCHUNK][4][8][32][4];   // 128KB
__device__ __align__(16) u32 g_w2frag[NCHUNK][8][16][32][4];  // 512KB

// ============================ low-level helpers =============================
__device__ __forceinline__ u32 smem_u32_of(const void* p) {
  u32 a;
  asm("{ .reg .u64 t; cvta.to.shared.u64 t, %1; cvt.u32.u64 %0, t; }" : "=r"(a) : "l"(p));
  return a;
}
__device__ __forceinline__ u32 swz(int r, int k) {   // 64-k SW128 image
  u32 off = ((u32)(r >> 3) << 10) | ((u32)(r & 7) << 7) | ((u32)k << 1);
  return off ^ ((off >> 3) & 0x70u);
}
__device__ __forceinline__ void ldsm4(u32 addr, u32 f[4]) {
  asm volatile("ldmatrix.sync.aligned.m8n8.x4.shared.b16 {%0,%1,%2,%3}, [%4];"
               : "=r"(f[0]), "=r"(f[1]), "=r"(f[2]), "=r"(f[3]) : "r"(addr));
}
__device__ __forceinline__ u32 a_addr(u32 img, int m0, int k0, int lr, int lg) {
  return img + swz(m0 + lr + ((lg & 1) << 3), k0 + ((lg >> 1) << 3));
}
__device__ __forceinline__ void mma16816(float c[4], const u32 a[4], u32 b0, u32 b1) {
  asm volatile(
    "mma.sync.aligned.m16n8k16.row.col.f32.f16.f16.f32 "
    "{%0,%1,%2,%3}, {%4,%5,%6,%7}, {%8,%9}, {%0,%1,%2,%3};"
    : "+f"(c[0]), "+f"(c[1]), "+f"(c[2]), "+f"(c[3])
    : "r"(a[0]), "r"(a[1]), "r"(a[2]), "r"(a[3]), "r"(b0), "r"(b1));
}

// ============================ threefry dropout ==============================
__device__ __forceinline__ u32 rotl32(u32 x, u32 r) { return __funnelshift_l(x, x, r); }
__device__ __forceinline__ void tf2x32(u32 x0, u32 x1, u32 &o0, u32 &o1) {
  const u32 ks0 = 0u, ks1 = 42u, ks2 = 0u ^ 42u ^ 0x1BD11BDAu;
  x0 += ks0; x1 += ks1;
#define TFR(r) { x0 += x1; x1 = rotl32(x1, r); x1 ^= x0; }
  TFR(13) TFR(15) TFR(26) TFR(6)
  x0 += ks1; x1 += ks2 + 1u;
  TFR(17) TFR(29) TFR(16) TFR(24)
  x0 += ks2; x1 += ks0 + 2u;
  TFR(13) TFR(15) TFR(26) TFR(6)
  x0 += ks0; x1 += ks1 + 3u;
  TFR(17) TFR(29) TFR(16) TFR(24)
  x0 += ks1; x1 += ks2 + 4u;
  TFR(13) TFR(15) TFR(26) TFR(6)
  x0 += ks2; x1 += ks0 + 5u;
#undef TFR
  o0 = x0; o1 = x1;
}
__device__ __forceinline__ bool drop_elem(u32 i) {   // validated rel_err 0.0 (R1)
  u32 o0, o1;
  tf2x32(0u, i, o0, o1);
  u32 bits = o0 ^ o1;
  float u = __uint_as_float((bits >> 9) | 0x3f800000u) - 1.0f;
  return u < 0.2f;
}

__device__ __forceinline__ u32 pack_h2(float a, float b) {
  return (u32)__half_as_ushort(__float2half_rn(a))
       | ((u32)__half_as_ushort(__float2half_rn(b)) << 16);
}

// ============================ prep kernel ===================================
// Pack W1/W2 (fp16-rounded) into per-lane MMA B-fragment order (R13 layout,
// verified correct by R13's exact rel_err match).
__global__ void prep_kernel(const float* __restrict__ W1,
                            const float* __restrict__ W2) {
  int idx = blockIdx.x * blockDim.x + threadIdx.x;
  const int NW1 = NCHUNK * 4 * 8 * 32 * 4;    // 32768 u32
  const int NW2 = NCHUNK * 8 * 16 * 32 * 4;   // 131072 u32
  if (idx < NW1) {
    int r = idx & 3, lane = (idx >> 2) & 31;
    int nt = (idx >> 7) & 7, kt = (idx >> 10) & 3, kc = idx >> 12;
    int gid = lane >> 2, tig = lane & 3;
    int n = kc * KC + nt * 16 + gid + ((r & 2) ? 8 : 0);
    int k = kt * 16 + 2 * tig + ((r & 1) ? 8 : 0);
    float w0 = (k     < LSEQ) ? W1[(size_t)k       * HDIM + n] : 0.0f;
    float w1 = (k + 1 < LSEQ) ? W1[(size_t)(k + 1) * HDIM + n] : 0.0f;
    g_w1frag[kc][kt][nt][lane][r] = pack_h2(w0, w1);
  } else if (idx < NW1 + NW2) {
    int j = idx - NW1;
    int r = j & 3, lane = (j >> 2) & 31;
    int nt = (j >> 7) & 15, kt = (j >> 11) & 7, kc = j >> 14;
    int gid = lane >> 2, tig = lane & 3;
    int n = nt * 16 + gid + ((r & 2) ? 8 : 0);
    int k = kc * KC + kt * 16 + 2 * tig + ((r & 1) ? 8 : 0);
    g_w2frag[kc][kt][nt][lane][r] =
        pack_h2(W2[(size_t)k * EDIM + n], W2[(size_t)(k + 1) * EDIM + n]);
  }
}

// ============================ main kernel ===================================
extern __shared__ __align__(1024) unsigned char smem_raw[];

__global__ void __launch_bounds__(NTHREADS, 2)
seqfc_main(const float* __restrict__ seq,
           const float* __restrict__ b1,
           const float* __restrict__ b2,
           float* __restrict__ out)
{
  const int tid  = threadIdx.x;
  const int wid  = tid >> 5;
  const int lane = tid & 31;
  const int lr   = lane & 7;
  const int lg   = lane >> 3;
  const int gid  = lane >> 2;
  const int tig  = lane & 3;
  const int wr   = wid >> 2;          // 2 row groups of 32
  const int wc   = wid & 3;           // 4 col groups
  const int row0 = blockIdx.x * MTILE;

  const u32 sm = smem_u32_of(smem_raw);

  // ---- X stage: fp32 staging -> mask+dropout -> fp16 SW128 image ----
  {
    float* xs = (float*)(smem_raw + SM_STAGE);     // stride 52
    const float* sp = seq + (size_t)row0 * LSEQ;
    for (int idx = tid; idx < MTILE * LSEQ; idx += NTHREADS) {
      int r = idx / LSEQ, k = idx - r * LSEQ;
      xs[r * 52 + k] = sp[idx];
    }
    __syncthreads();

    const int xrow = tid >> 2;          // 4 threads per row
    const int q    = tid & 3;
    float xv[16];
#pragma unroll
    for (int i = 0; i < 16; ++i) {
      int k = q * 16 + i;
      xv[i] = (k < LSEQ) ? xs[xrow * 52 + k] : 0.0f;
    }
    int f = LSEQ;
#pragma unroll
    for (int i = 15; i >= 0; --i) {
      int k = q * 16 + i;
      if (k < LSEQ && xv[i] == -1.0f) f = k;
    }
    f = min(f, __shfl_xor_sync(0xffffffffu, f, 1));
    f = min(f, __shfl_xor_sync(0xffffffffu, f, 2));
    const u32 gb = (u32)(row0 + xrow) * (u32)LSEQ;
#pragma unroll
    for (int i = 0; i < 16; ++i) {
      int k = q * 16 + i;
      if (k < f && drop_elem(gb + (u32)k)) xv[i] = 0.0f;
    }
#pragma unroll
    for (int c = 0; c < 8; ++c) {
      u32 o = swz(xrow, q * 16 + 2 * c);
      *(u32*)(smem_raw + SM_X + o) = pack_h2(xv[2 * c], xv[2 * c + 1]);
    }
  }
  __syncthreads();            // X image ready

  // ---- GEMM2 accumulators: warp tile = 32 rows x 64 cols ----
  float acc2[2][8][4];
#pragma unroll
  for (int mt = 0; mt < 2; ++mt)
#pragma unroll
    for (int j = 0; j < 8; ++j)
#pragma unroll
      for (int q = 0; q < 4; ++q) acc2[mt][j][q] = 0.0f;

  // ---- chunk loop: 8 chunks of K=128, ONE bar per chunk ----
  for (int kc = 0; kc < NCHUNK; ++kc) {
    const u32 hbase = (u32)(SM_H0 + ((kc & 1) << 14));

    // ---- twin GEMM1 sub-blocks: cols [sub*64 + wc*16, +16) ----
#pragma unroll
    for (int sub = 0; sub < 2; ++sub) {
      // bias for this sub-block's convert
      float bv[4];
      {
        const int bb = kc * KC + sub * 64;
#pragma unroll
        for (int j = 0; j < 2; ++j) {
          int cc = bb + wc * 16 + j * 8 + 2 * tig;
          bv[j * 2]     = __ldg(b1 + cc);
          bv[j * 2 + 1] = __ldg(b1 + cc + 1);
        }
      }

      float acc1[2][2][4];
#pragma unroll
      for (int mt = 0; mt < 2; ++mt)
#pragma unroll
        for (int j = 0; j < 2; ++j)
#pragma unroll
          for (int q = 0; q < 4; ++q) acc1[mt][j][q] = 0.0f;

#pragma unroll
      for (int kt = 0; kt < 4; ++kt) {
        const int k0 = kt * 16;
        u32 ax0[4], ax1[4];
        ldsm4(a_addr(sm + SM_X, wr * 32,      k0, lr, lg), ax0);
        ldsm4(a_addr(sm + SM_X, wr * 32 + 16, k0, lr, lg), ax1);
        const uint4 bw = __ldg((const uint4*)g_w1frag[kc][kt][sub * 4 + wc][lane]);
        mma16816(acc1[0][0], ax0, bw.x, bw.y);
        mma16816(acc1[0][1], ax0, bw.z, bw.w);
        mma16816(acc1[1][0], ax1, bw.x, bw.y);
        mma16816(acc1[1][1], ax1, bw.z, bw.w);
      }

      // convert: bias + relu -> h sub-image (8KB each)
      const u32 hoff = hbase + ((u32)sub << 13);
#pragma unroll
      for (int mt = 0; mt < 2; ++mt) {
        const int r0 = wr * 32 + mt * 16 + gid;
#pragma unroll
        for (int j = 0; j < 2; ++j) {
          const int cc = wc * 16 + j * 8 + 2 * tig;
          float v0 = fmaxf(acc1[mt][j][0] + bv[j * 2],     0.0f);
          float v1 = fmaxf(acc1[mt][j][1] + bv[j * 2 + 1], 0.0f);
          float v2 = fmaxf(acc1[mt][j][2] + bv[j * 2],     0.0f);
          float v3 = fmaxf(acc1[mt][j][3] + bv[j * 2 + 1], 0.0f);
          *(u32*)(smem_raw + hoff + swz(r0, cc))     = pack_h2(v0, v1);
          *(u32*)(smem_raw + hoff + swz(r0 + 8, cc)) = pack_h2(v2, v3);
        }
      }
    }
    __syncthreads();          // h[kc] (128 k) visible; fences prior-buf reuse

    // ---- GEMM2(kc): warp tile 32 x 64 over K=128 (8 kt) ----
#pragma unroll
    for (int kt = 0; kt < 8; ++kt) {
      const u32 himg = hbase + ((u32)(kt >> 2) << 13);
      const int k0 = (kt & 3) * 16;
      u32 ah0[4], ah1[4];
      ldsm4(a_addr(sm + himg, wr * 32,      k0, lr, lg), ah0);
      ldsm4(a_addr(sm + himg, wr * 32 + 16, k0, lr, lg), ah1);
#pragma unroll
      for (int half = 0; half < 2; ++half) {
        uint4 bw0 = __ldg((const uint4*)g_w2frag[kc][kt][wc * 4 + half * 2][lane]);
        uint4 bw1 = __ldg((const uint4*)g_w2frag[kc][kt][wc * 4 + half * 2 + 1][lane]);
        const int jb = half * 4;
        mma16816(acc2[0][jb],     ah0, bw0.x, bw0.y);
        mma16816(acc2[0][jb + 1], ah0, bw0.z, bw0.w);
        mma16816(acc2[1][jb],     ah1, bw0.x, bw0.y);
        mma16816(acc2[1][jb + 1], ah1, bw0.z, bw0.w);
        mma16816(acc2[0][jb + 2], ah0, bw1.x, bw1.y);
        mma16816(acc2[0][jb + 3], ah0, bw1.z, bw1.w);
        mma16816(acc2[1][jb + 2], ah1, bw1.x, bw1.y);
        mma16816(acc2[1][jb + 3], ah1, bw1.z, bw1.w);
      }
    }
    // no trailing bar: next chunk writes the other h buffer.
  }

  // ---- epilogue: + b2 (__ldg), store ----
#pragma unroll
  for (int mt = 0; mt < 2; ++mt) {
    const int r0 = row0 + wr * 32 + mt * 16 + gid;
#pragma unroll
    for (int j = 0; j < 8; ++j) {
      const int c = wc * 64 + j * 8 + 2 * tig;
      const float bb0 = __ldg(b2 + c), bb1 = __ldg(b2 + c + 1);
      float2 va = make_float2(acc2[mt][j][0] + bb0, acc2[mt][j][1] + bb1);
      float2 vb = make_float2(acc2[mt][j][2] + bb0, acc2[mt][j][3] + bb1);
      *(float2*)(out + (size_t)r0 * EDIM + c)       = va;
      *(float2*)(out + (size_t)(r0 + 8) * EDIM + c) = vb;
    }
  }
}

// ============================ launch ========================================
extern "C" void kernel_launch(void* const* d_in, const int* in_sizes, int n_in,
                              void* d_out, int out_size) {
  (void)in_sizes; (void)n_in; (void)out_size;
  const float* seq = (const float*)d_in[0];
  const float* W1  = (const float*)d_in[1];
  const float* b1  = (const float*)d_in[2];
  const float* W2  = (const float*)d_in[3];
  const float* b2  = (const float*)d_in[4];

  cudaFuncSetAttribute(seqfc_main, cudaFuncAttributeMaxDynamicSharedMemorySize,
                       SMEM_TOTAL);

  const int prep_total = NCHUNK * 4 * 8 * 32 * 4 + NCHUNK * 8 * 16 * 32 * 4;
  prep_kernel<<<(prep_total + 255) / 256, 256>>>(W1, W2);
  seqfc_main<<<B_TOTAL / MTILE, NTHREADS, SMEM_TOTAL>>>(seq, b1, b2, (float*)d_out);
}